// round 6
// baseline (speedup 1.0000x reference)
#include <cuda_runtime.h>

// Problem constants
#define B_TOT    4096
#define T_LEN    512
#define D_IN     7
#define H        64
#define G        256      // 4*H gates per layer
#define OUT_D    4
#define BTILE    32       // batch rows per CTA
#define NTHREADS 512      // thread = (8 rows) x (2 gates of one unit)
#define RP       36       // h smem pitch in floats
#define XP       32       // x smem pitch

typedef unsigned long long u64;

__device__ __forceinline__ u64 pack2(float v) {
    u64 r; asm("mov.b64 %0, {%1, %1};" : "=l"(r) : "f"(v)); return r;
}
__device__ __forceinline__ void unpack2(u64 v, float& a, float& b) {
    asm("mov.b64 {%0, %1}, %2;" : "=f"(a), "=f"(b) : "l"(v));
}
__device__ __forceinline__ u64 ffma2(u64 a, u64 b, u64 c) {
    u64 d; asm("fma.rn.f32x2 %0, %1, %2, %3;" : "=l"(d) : "l"(a), "l"(b), "l"(c)); return d;
}

__device__ __forceinline__ float sigf(float x) {
    return __fdividef(1.0f, 1.0f + __expf(-x));
}
__device__ __forceinline__ float tanhf_fast(float x) {
    return __fdividef(2.0f, 1.0f + __expf(-2.0f * x)) - 1.0f;
}

__global__ __launch_bounds__(NTHREADS, 1)
void lstm_fused_kernel(const float* __restrict__ x,
                       const float* __restrict__ W_ih0, const float* __restrict__ W_hh0,
                       const float* __restrict__ b_ih0, const float* __restrict__ b_hh0,
                       const float* __restrict__ W_ih1, const float* __restrict__ W_hh1,
                       const float* __restrict__ b_ih1, const float* __restrict__ b_hh1,
                       const float* __restrict__ W_fc,  const float* __restrict__ b_fc,
                       float* __restrict__ out)
{
    extern __shared__ float smem[];
    // weight layout: [k][unit][gate i,f,g,o] -> idx = k*256 + u*4 + g
    float* s_wih0 = smem;                    // [7][256]
    float* s_whh0 = s_wih0 + D_IN * G;       // [64][256]
    float* s_wih1 = s_whh0 + H * G;          // [64][256]
    float* s_whh1 = s_wih1 + H * G;          // [64][256]
    float* s_b0   = s_whh1 + H * G;          // [256]
    float* s_b1   = s_b0 + G;                // [256]
    float* s_wfc  = s_b1 + G;                // [4][64]
    float* s_bfc  = s_wfc + OUT_D * H;       // [8]
    float* s_h0   = s_bfc + 8;               // [64][RP]  [unit][row]
    float* s_h1   = s_h0 + H * RP;           // [64][RP]
    float* s_x    = s_h1 + H * RP;           // [7][XP]   [d][row]

    const int tid  = threadIdx.x;
    const int l    = tid & 31;
    const int w    = tid >> 5;               // warp 0..15
    const int rg   = w >> 2;                 // 0..3 : batch-row group (8 rows)
    const int uhi  = w & 3;                  // unit high bits
    const int u    = uhi * 16 + (l >> 1);    // hidden unit 0..63
    const int half = l & 1;                  // 0 -> gates (i,f), 1 -> gates (g,o)
    const int r0   = rg * 8;                 // first row this warp's FFMA covers
    const int rb   = r0 + half * 4;          // rows this thread updates/stores
    const int wcol = u * 4 + half * 2;       // float column in a weight k-row

    // ---- stage weights into smem, transposed + gate-interleaved ----
    for (int idx = tid; idx < D_IN * G; idx += NTHREADS) {
        int d = idx >> 8, r = idx & 255, uu = r >> 2, gb = r & 3;
        s_wih0[idx] = W_ih0[(gb * H + uu) * D_IN + d];
    }
    for (int idx = tid; idx < H * G; idx += NTHREADS) {
        int k = idx >> 8, r = idx & 255, uu = r >> 2, gb = r & 3;
        int row = gb * H + uu;
        s_whh0[idx] = W_hh0[row * H + k];
        s_wih1[idx] = W_ih1[row * H + k];
        s_whh1[idx] = W_hh1[row * H + k];
    }
    for (int r = tid; r < G; r += NTHREADS) {
        int uu = r >> 2, gb = r & 3, row = gb * H + uu;
        s_b0[r] = b_ih0[row] + b_hh0[row];
        s_b1[r] = b_ih1[row] + b_hh1[row];
    }
    for (int i = tid; i < OUT_D * H; i += NTHREADS) s_wfc[i] = W_fc[i];
    if (tid < OUT_D) s_bfc[tid] = b_fc[tid];
    for (int i = tid; i < H * RP; i += NTHREADS) { s_h0[i] = 0.0f; s_h1[i] = 0.0f; }

    // x staging role: 224 threads each own one (row, d)
    const int  bb      = blockIdx.x * BTILE;
    const bool xactive = tid < BTILE * D_IN;
    const int  xrow    = tid / D_IN;
    const int  xd      = tid - xrow * D_IN;
    const float* xg    = x + ((size_t)(bb + xrow) * T_LEN) * D_IN + xd;

    if (xactive) s_x[xd * XP + xrow] = __ldg(xg);   // prestage x[0]
    __syncthreads();

    // duplicated bias pairs for this thread's 2 gates, once for all steps
    u64 b0x, b0y, b1x, b1y;
    {
        float2 t0 = *(const float2*)&s_b0[wcol];
        b0x = pack2(t0.x); b0y = pack2(t0.y);
        float2 t1 = *(const float2*)&s_b1[wcol];
        b1x = pack2(t1.x); b1y = pack2(t1.y);
    }

    float c0[4] = {0.f, 0.f, 0.f, 0.f};
    float c1[4] = {0.f, 0.f, 0.f, 0.f};

    for (int t = 0; t < T_LEN; t++) {
        // accumulators: a[g*4 + rp] = gate g (of this thread's 2) for row pair rp
        u64 a0[8], a1[8];
        #pragma unroll
        for (int rp = 0; rp < 4; rp++) {
            a0[rp] = b0x; a0[4 + rp] = b0y;
            a1[rp] = b1x; a1[4 + rp] = b1y;
        }

        // ---- phase 1: h0 @ W_hh0^T and h1 @ W_hh1^T ----
        #pragma unroll 2
        for (int k = 0; k < H; k++) {
            float2 w0 = *(const float2*)&s_whh0[k * G + wcol];
            float2 w1 = *(const float2*)&s_whh1[k * G + wcol];
            u64 w0a = pack2(w0.x), w0b = pack2(w0.y);
            u64 w1a = pack2(w1.x), w1b = pack2(w1.y);
            ulonglong2 h0p = *(const ulonglong2*)&s_h0[k * RP + r0];
            ulonglong2 h0q = *(const ulonglong2*)&s_h0[k * RP + r0 + 4];
            ulonglong2 h1p = *(const ulonglong2*)&s_h1[k * RP + r0];
            ulonglong2 h1q = *(const ulonglong2*)&s_h1[k * RP + r0 + 4];
            a0[0] = ffma2(w0a, h0p.x, a0[0]);
            a0[1] = ffma2(w0a, h0p.y, a0[1]);
            a0[2] = ffma2(w0a, h0q.x, a0[2]);
            a0[3] = ffma2(w0a, h0q.y, a0[3]);
            a0[4] = ffma2(w0b, h0p.x, a0[4]);
            a0[5] = ffma2(w0b, h0p.y, a0[5]);
            a0[6] = ffma2(w0b, h0q.x, a0[6]);
            a0[7] = ffma2(w0b, h0q.y, a0[7]);
            a1[0] = ffma2(w1a, h1p.x, a1[0]);
            a1[1] = ffma2(w1a, h1p.y, a1[1]);
            a1[2] = ffma2(w1a, h1q.x, a1[2]);
            a1[3] = ffma2(w1a, h1q.y, a1[3]);
            a1[4] = ffma2(w1b, h1p.x, a1[4]);
            a1[5] = ffma2(w1b, h1p.y, a1[5]);
            a1[6] = ffma2(w1b, h1q.x, a1[6]);
            a1[7] = ffma2(w1b, h1q.y, a1[7]);
        }

        // x @ W_ih0^T
        #pragma unroll
        for (int d = 0; d < D_IN; d++) {
            float2 wx = *(const float2*)&s_wih0[d * G + wcol];
            u64 wxa = pack2(wx.x), wxb = pack2(wx.y);
            ulonglong2 xp = *(const ulonglong2*)&s_x[d * XP + r0];
            ulonglong2 xq = *(const ulonglong2*)&s_x[d * XP + r0 + 4];
            a0[0] = ffma2(wxa, xp.x, a0[0]);
            a0[1] = ffma2(wxa, xp.y, a0[1]);
            a0[2] = ffma2(wxa, xq.x, a0[2]);
            a0[3] = ffma2(wxa, xq.y, a0[3]);
            a0[4] = ffma2(wxb, xp.x, a0[4]);
            a0[5] = ffma2(wxb, xp.y, a0[5]);
            a0[6] = ffma2(wxb, xq.x, a0[6]);
            a0[7] = ffma2(wxb, xq.y, a0[7]);
        }

        // ---- layer-0 cell update (gate exchange with lane partner) ----
        {
            u64 recv[4];
            #pragma unroll
            for (int g = 0; g < 2; g++)
                #pragma unroll
                for (int rp = 0; rp < 2; rp++) {
                    u64 snd = half ? a0[g * 4 + rp] : a0[g * 4 + 2 + rp];
                    recv[g * 2 + rp] = __shfl_xor_sync(0xffffffffu, snd, 1);
                }
            float hn[4];
            #pragma unroll
            for (int rp = 0; rp < 2; rp++) {
                u64 ipr = half ? recv[rp]     : a0[rp];
                u64 fpr = half ? recv[2 + rp] : a0[4 + rp];
                u64 gpr = half ? a0[2 + rp]   : recv[rp];
                u64 opr = half ? a0[6 + rp]   : recv[2 + rp];
                float i0, i1, f0, f1, g0, g1, o0, o1;
                unpack2(ipr, i0, i1); unpack2(fpr, f0, f1);
                unpack2(gpr, g0, g1); unpack2(opr, o0, o1);
                float iA = sigf(i0), fA = sigf(f0), gA = tanhf_fast(g0), oA = sigf(o0);
                c0[rp * 2]     = fA * c0[rp * 2] + iA * gA;
                hn[rp * 2]     = oA * tanhf_fast(c0[rp * 2]);
                float iB = sigf(i1), fB = sigf(f1), gB = tanhf_fast(g1), oB = sigf(o1);
                c0[rp * 2 + 1] = fB * c0[rp * 2 + 1] + iB * gB;
                hn[rp * 2 + 1] = oB * tanhf_fast(c0[rp * 2 + 1]);
            }
            __syncthreads();   // all reads of s_h0/s_h1/s_x for this step done
            *(float4*)&s_h0[u * RP + rb] = make_float4(hn[0], hn[1], hn[2], hn[3]);
        }
        __syncthreads();       // new h0 visible

        // ---- phase 2: h0(new) @ W_ih1^T ----
        #pragma unroll 4
        for (int k = 0; k < H; k++) {
            float2 wv = *(const float2*)&s_wih1[k * G + wcol];
            u64 wa = pack2(wv.x), wb = pack2(wv.y);
            ulonglong2 hp = *(const ulonglong2*)&s_h0[k * RP + r0];
            ulonglong2 hq = *(const ulonglong2*)&s_h0[k * RP + r0 + 4];
            a1[0] = ffma2(wa, hp.x, a1[0]);
            a1[1] = ffma2(wa, hp.y, a1[1]);
            a1[2] = ffma2(wa, hq.x, a1[2]);
            a1[3] = ffma2(wa, hq.y, a1[3]);
            a1[4] = ffma2(wb, hp.x, a1[4]);
            a1[5] = ffma2(wb, hp.y, a1[5]);
            a1[6] = ffma2(wb, hq.x, a1[6]);
            a1[7] = ffma2(wb, hq.y, a1[7]);
        }

        // ---- layer-1 cell update; phase 2 never reads s_h1, safe to write ----
        {
            u64 recv[4];
            #pragma unroll
            for (int g = 0; g < 2; g++)
                #pragma unroll
                for (int rp = 0; rp < 2; rp++) {
                    u64 snd = half ? a1[g * 4 + rp] : a1[g * 4 + 2 + rp];
                    recv[g * 2 + rp] = __shfl_xor_sync(0xffffffffu, snd, 1);
                }
            float hn[4];
            #pragma unroll
            for (int rp = 0; rp < 2; rp++) {
                u64 ipr = half ? recv[rp]     : a1[rp];
                u64 fpr = half ? recv[2 + rp] : a1[4 + rp];
                u64 gpr = half ? a1[2 + rp]   : recv[rp];
                u64 opr = half ? a1[6 + rp]   : recv[2 + rp];
                float i0, i1, f0, f1, g0, g1, o0, o1;
                unpack2(ipr, i0, i1); unpack2(fpr, f0, f1);
                unpack2(gpr, g0, g1); unpack2(opr, o0, o1);
                float iA = sigf(i0), fA = sigf(f0), gA = tanhf_fast(g0), oA = sigf(o0);
                c1[rp * 2]     = fA * c1[rp * 2] + iA * gA;
                hn[rp * 2]     = oA * tanhf_fast(c1[rp * 2]);
                float iB = sigf(i1), fB = sigf(f1), gB = tanhf_fast(g1), oB = sigf(o1);
                c1[rp * 2 + 1] = fB * c1[rp * 2 + 1] + iB * gB;
                hn[rp * 2 + 1] = oB * tanhf_fast(c1[rp * 2 + 1]);
            }
            *(float4*)&s_h1[u * RP + rb] = make_float4(hn[0], hn[1], hn[2], hn[3]);
        }

        // stage x[t+1] (s_x readers for step t finished before sync #1)
        if (xactive && t + 1 < T_LEN)
            s_x[xd * XP + xrow] = __ldg(xg + (size_t)(t + 1) * D_IN);

        __syncthreads();   // h1 + x[t+1] complete before next step reads them
    }

    // ---- epilogue: out[b] = h1_last @ W_fc^T + b_fc (warp 0, lane = row) ----
    if (tid < 32) {
        float acc[OUT_D];
        #pragma unroll
        for (int o = 0; o < OUT_D; o++) acc[o] = s_bfc[o];
        #pragma unroll 8
        for (int k = 0; k < H; k++) {
            float hv = s_h1[k * RP + tid];   // h1[row=tid][k]
            #pragma unroll
            for (int o = 0; o < OUT_D; o++) acc[o] += hv * s_wfc[o * H + k];
        }
        int b = bb + tid;
        #pragma unroll
        for (int o = 0; o < OUT_D; o++)
            out[(size_t)b * OUT_D + o] = acc[o];
    }
}

extern "C" void kernel_launch(void* const* d_in, const int* in_sizes, int n_in,
                              void* d_out, int out_size)
{
    const float* x     = (const float*)d_in[0];
    const float* W_ih0 = (const float*)d_in[1];
    const float* W_hh0 = (const float*)d_in[2];
    const float* b_ih0 = (const float*)d_in[3];
    const float* b_hh0 = (const float*)d_in[4];
    const float* W_ih1 = (const float*)d_in[5];
    const float* W_hh1 = (const float*)d_in[6];
    const float* b_ih1 = (const float*)d_in[7];
    const float* b_hh1 = (const float*)d_in[8];
    const float* W_fc  = (const float*)d_in[9];
    const float* b_fc  = (const float*)d_in[10];
    float* out = (float*)d_out;

    const size_t smem_floats = (size_t)D_IN * G + 3 * (size_t)H * G + 2 * G
                             + OUT_D * H + 8 + 2 * (size_t)H * RP + D_IN * XP;
    const size_t smem_bytes = smem_floats * sizeof(float);   // 226,208 B

    cudaFuncSetAttribute(lstm_fused_kernel,
                         cudaFuncAttributeMaxDynamicSharedMemorySize,
                         (int)smem_bytes);

    lstm_fused_kernel<<<B_TOT / BTILE, NTHREADS, smem_bytes>>>(
        x, W_ih0, W_hh0, b_ih0, b_hh0,
        W_ih1, W_hh1, b_ih1, b_hh1, W_fc, b_fc, out);
}

// round 7
// speedup vs baseline: 1.1326x; 1.1326x over previous
#include <cuda_runtime.h>

// Problem constants
#define B_TOT    4096
#define T_LEN    512
#define D_IN     7
#define H        64
#define G        256      // 4*H gates per layer
#define OUT_D    4
#define BTILE    32       // batch rows per CTA
#define NTHREADS 256      // thread = (8 batch rows) x (1 unit = 4 gates)
#define RP       36       // h smem pitch in floats
#define XP       32       // x smem pitch: s_x[d*XP + row]

typedef unsigned long long u64;

__device__ __forceinline__ u64 pack2(float v) {
    u64 r; asm("mov.b64 %0, {%1, %1};" : "=l"(r) : "f"(v)); return r;
}
__device__ __forceinline__ void unpack2(u64 v, float& a, float& b) {
    asm("mov.b64 {%0, %1}, %2;" : "=f"(a), "=f"(b) : "l"(v));
}
__device__ __forceinline__ u64 ffma2(u64 a, u64 b, u64 c) {
    u64 d; asm("fma.rn.f32x2 %0, %1, %2, %3;" : "=l"(d) : "l"(a), "l"(b), "l"(c)); return d;
}

__device__ __forceinline__ float sigf(float x) {
    return __fdividef(1.0f, 1.0f + __expf(-x));
}
__device__ __forceinline__ float tanhf_fast(float x) {
    return __fdividef(2.0f, 1.0f + __expf(-2.0f * x)) - 1.0f;
}

__global__ __launch_bounds__(NTHREADS, 1)
void lstm_fused_kernel(const float* __restrict__ x,
                       const float* __restrict__ W_ih0, const float* __restrict__ W_hh0,
                       const float* __restrict__ b_ih0, const float* __restrict__ b_hh0,
                       const float* __restrict__ W_ih1, const float* __restrict__ W_hh1,
                       const float* __restrict__ b_ih1, const float* __restrict__ b_hh1,
                       const float* __restrict__ W_fc,  const float* __restrict__ b_fc,
                       float* __restrict__ out)
{
    extern __shared__ float smem[];
    // weight layout: [k][unit][gate i,f,g,o] -> idx = k*256 + u*4 + g
    float* s_wih0 = smem;                    // [7][256]
    float* s_whh0 = s_wih0 + D_IN * G;       // [64][256]
    float* s_wih1 = s_whh0 + H * G;          // [64][256]
    float* s_whh1 = s_wih1 + H * G;          // [64][256]
    float* s_b0   = s_whh1 + H * G;          // [256]
    float* s_b1   = s_b0 + G;                // [256]
    float* s_wfc  = s_b1 + G;                // [4][64]
    float* s_bfc  = s_wfc + OUT_D * H;       // [8]
    float* s_h0   = s_bfc + 8;               // [64][RP]  [unit][row]
    float* s_h1   = s_h0 + H * RP;           // [64][RP]
    float* s_x    = s_h1 + H * RP;           // [7][XP]   [d][row]

    const int tid  = threadIdx.x;
    const int urow = tid >> 6;               // 0..3 : batch-row group
    const int ucol = tid & 63;               // 0..63: hidden unit
    const int r0   = urow * 8;               // first of this thread's 8 rows

    // ---- stage weights into smem, transposed + gate-interleaved ----
    for (int idx = tid; idx < D_IN * G; idx += NTHREADS) {
        int d = idx >> 8, r = idx & 255, u = r >> 2, gb = r & 3;
        s_wih0[idx] = W_ih0[(gb * H + u) * D_IN + d];
    }
    for (int idx = tid; idx < H * G; idx += NTHREADS) {
        int k = idx >> 8, r = idx & 255, u = r >> 2, gb = r & 3;
        int row = gb * H + u;
        s_whh0[idx] = W_hh0[row * H + k];
        s_wih1[idx] = W_ih1[row * H + k];
        s_whh1[idx] = W_hh1[row * H + k];
    }
    for (int r = tid; r < G; r += NTHREADS) {
        int u = r >> 2, gb = r & 3, row = gb * H + u;
        s_b0[r] = b_ih0[row] + b_hh0[row];
        s_b1[r] = b_ih1[row] + b_hh1[row];
    }
    for (int i = tid; i < OUT_D * H; i += NTHREADS) s_wfc[i] = W_fc[i];
    if (tid < OUT_D) s_bfc[tid] = b_fc[tid];
    for (int i = tid; i < H * RP; i += NTHREADS) { s_h0[i] = 0.0f; s_h1[i] = 0.0f; }

    // x staging role: 224 threads each own one (row, d)
    const int  bb      = blockIdx.x * BTILE;
    const bool xactive = tid < BTILE * D_IN;
    const int  xrow    = tid / D_IN;
    const int  xd      = tid - xrow * D_IN;
    const float* xg    = x + ((size_t)(bb + xrow) * T_LEN) * D_IN + xd;

    if (xactive) s_x[xd * XP + xrow] = __ldg(xg);   // prestage x[0]
    __syncthreads();

    // bias pairs for this thread's unit, held in regs across all steps
    u64 b0p0, b0p1, b1p0, b1p1;
    {
        ulonglong2 t0 = *(const ulonglong2*)&s_b0[ucol * 4];
        b0p0 = t0.x; b0p1 = t0.y;
        ulonglong2 t1 = *(const ulonglong2*)&s_b1[ucol * 4];
        b1p0 = t1.x; b1p1 = t1.y;
    }

    float c0[8], c1[8];
    #pragma unroll
    for (int r = 0; r < 8; r++) { c0[r] = 0.f; c1[r] = 0.f; }

    // Pipelined recurrence: iteration t computes h0(t) AND h1(t-1),
    // both from state produced by iteration t-1 (h0(t-1), h1(t-2)).
    for (int t = 0; t < T_LEN; t++) {
        u64 a0[16], a1[16];
        #pragma unroll
        for (int r = 0; r < 8; r++) {
            a0[2*r] = b0p0; a0[2*r+1] = b0p1;
            a1[2*r] = b1p0; a1[2*r+1] = b1p1;
        }

        // ---- fused GEMMs: Whh0@h0old, Wih1@h0old, Whh1@h1old ----
        #pragma unroll 2
        for (int k = 0; k < H; k++) {
            ulonglong2 w0 = *(const ulonglong2*)&s_whh0[k * G + ucol * 4];
            ulonglong2 w1 = *(const ulonglong2*)&s_whh1[k * G + ucol * 4];
            ulonglong2 w2 = *(const ulonglong2*)&s_wih1[k * G + ucol * 4];
            float4 h0a = *(const float4*)&s_h0[k * RP + r0];
            float4 h0b = *(const float4*)&s_h0[k * RP + r0 + 4];
            float4 h1a = *(const float4*)&s_h1[k * RP + r0];
            float4 h1b = *(const float4*)&s_h1[k * RP + r0 + 4];
            float h0s[8] = {h0a.x, h0a.y, h0a.z, h0a.w, h0b.x, h0b.y, h0b.z, h0b.w};
            float h1s[8] = {h1a.x, h1a.y, h1a.z, h1a.w, h1b.x, h1b.y, h1b.z, h1b.w};
            #pragma unroll
            for (int r = 0; r < 8; r++) {
                u64 h0p = pack2(h0s[r]);
                u64 h1p = pack2(h1s[r]);
                a0[2*r]   = ffma2(w0.x, h0p, a0[2*r]);
                a0[2*r+1] = ffma2(w0.y, h0p, a0[2*r+1]);
                a1[2*r]   = ffma2(w1.x, h1p, a1[2*r]);
                a1[2*r+1] = ffma2(w1.y, h1p, a1[2*r+1]);
                a1[2*r]   = ffma2(w2.x, h0p, a1[2*r]);
                a1[2*r+1] = ffma2(w2.y, h0p, a1[2*r+1]);
            }
        }

        // x(t) @ W_ih0^T
        #pragma unroll
        for (int d = 0; d < D_IN; d++) {
            ulonglong2 w = *(const ulonglong2*)&s_wih0[d * G + ucol * 4];
            float4 xa = *(const float4*)&s_x[d * XP + r0];
            float4 xb = *(const float4*)&s_x[d * XP + r0 + 4];
            float xs[8] = {xa.x, xa.y, xa.z, xa.w, xb.x, xb.y, xb.z, xb.w};
            #pragma unroll
            for (int r = 0; r < 8; r++) {
                u64 xp = pack2(xs[r]);
                a0[2*r]   = ffma2(w.x, xp, a0[2*r]);
                a0[2*r+1] = ffma2(w.y, xp, a0[2*r+1]);
            }
        }

        // layer-0 cell update -> h0(t)
        float h0nv[8];
        #pragma unroll
        for (int r = 0; r < 8; r++) {
            float gi, gf, gg, go;
            unpack2(a0[2*r],   gi, gf);
            unpack2(a0[2*r+1], gg, go);
            float i_ = sigf(gi), f_ = sigf(gf), g_ = tanhf_fast(gg), o_ = sigf(go);
            c0[r] = f_ * c0[r] + i_ * g_;
            h0nv[r] = o_ * tanhf_fast(c0[r]);
        }

        // layer-1 cell update -> h1(t-1)  (skip at t==0: h1(-1) = 0)
        float h1nv[8];
        if (t > 0) {
            #pragma unroll
            for (int r = 0; r < 8; r++) {
                float gi, gf, gg, go;
                unpack2(a1[2*r],   gi, gf);
                unpack2(a1[2*r+1], gg, go);
                float i_ = sigf(gi), f_ = sigf(gf), g_ = tanhf_fast(gg), o_ = sigf(go);
                c1[r] = f_ * c1[r] + i_ * g_;
                h1nv[r] = o_ * tanhf_fast(c1[r]);
            }
        }

        __syncthreads();   // all reads of s_h0/s_h1/s_x for this step done
        *(float4*)&s_h0[ucol * RP + r0]     = make_float4(h0nv[0], h0nv[1], h0nv[2], h0nv[3]);
        *(float4*)&s_h0[ucol * RP + r0 + 4] = make_float4(h0nv[4], h0nv[5], h0nv[6], h0nv[7]);
        if (t > 0) {
            *(float4*)&s_h1[ucol * RP + r0]     = make_float4(h1nv[0], h1nv[1], h1nv[2], h1nv[3]);
            *(float4*)&s_h1[ucol * RP + r0 + 4] = make_float4(h1nv[4], h1nv[5], h1nv[6], h1nv[7]);
        }

        // stage x(t+1)
        if (xactive && t + 1 < T_LEN)
            s_x[xd * XP + xrow] = __ldg(xg + (size_t)(t + 1) * D_IN);

        __syncthreads();   // new h0/h1/x visible before next iteration
    }

    // ---- pipeline drain: compute h1(T-1) from h0(T-1), h1(T-2) ----
    {
        u64 a1[16];
        #pragma unroll
        for (int r = 0; r < 8; r++) { a1[2*r] = b1p0; a1[2*r+1] = b1p1; }

        #pragma unroll 2
        for (int k = 0; k < H; k++) {
            ulonglong2 w1 = *(const ulonglong2*)&s_whh1[k * G + ucol * 4];
            ulonglong2 w2 = *(const ulonglong2*)&s_wih1[k * G + ucol * 4];
            float4 h0a = *(const float4*)&s_h0[k * RP + r0];
            float4 h0b = *(const float4*)&s_h0[k * RP + r0 + 4];
            float4 h1a = *(const float4*)&s_h1[k * RP + r0];
            float4 h1b = *(const float4*)&s_h1[k * RP + r0 + 4];
            float h0s[8] = {h0a.x, h0a.y, h0a.z, h0a.w, h0b.x, h0b.y, h0b.z, h0b.w};
            float h1s[8] = {h1a.x, h1a.y, h1a.z, h1a.w, h1b.x, h1b.y, h1b.z, h1b.w};
            #pragma unroll
            for (int r = 0; r < 8; r++) {
                u64 h0p = pack2(h0s[r]);
                u64 h1p = pack2(h1s[r]);
                a1[2*r]   = ffma2(w1.x, h1p, a1[2*r]);
                a1[2*r+1] = ffma2(w1.y, h1p, a1[2*r+1]);
                a1[2*r]   = ffma2(w2.x, h0p, a1[2*r]);
                a1[2*r+1] = ffma2(w2.y, h0p, a1[2*r+1]);
            }
        }

        float h1nv[8];
        #pragma unroll
        for (int r = 0; r < 8; r++) {
            float gi, gf, gg, go;
            unpack2(a1[2*r],   gi, gf);
            unpack2(a1[2*r+1], gg, go);
            float i_ = sigf(gi), f_ = sigf(gf), g_ = tanhf_fast(gg), o_ = sigf(go);
            c1[r] = f_ * c1[r] + i_ * g_;
            h1nv[r] = o_ * tanhf_fast(c1[r]);
        }
        __syncthreads();   // reads of s_h1 (h1(T-2)) done everywhere
        *(float4*)&s_h1[ucol * RP + r0]     = make_float4(h1nv[0], h1nv[1], h1nv[2], h1nv[3]);
        *(float4*)&s_h1[ucol * RP + r0 + 4] = make_float4(h1nv[4], h1nv[5], h1nv[6], h1nv[7]);
        __syncthreads();   // final h1 visible
    }

    // ---- epilogue: out[b] = h1_last @ W_fc^T + b_fc (warp 0, lane = row) ----
    if (tid < 32) {
        float acc[OUT_D];
        #pragma unroll
        for (int o = 0; o < OUT_D; o++) acc[o] = s_bfc[o];
        #pragma unroll 8
        for (int k = 0; k < H; k++) {
            float hv = s_h1[k * RP + tid];   // h1[row=tid][k]
            #pragma unroll
            for (int o = 0; o < OUT_D; o++) acc[o] += hv * s_wfc[o * H + k];
        }
        int b = bb + tid;
        #pragma unroll
        for (int o = 0; o < OUT_D; o++)
            out[(size_t)b * OUT_D + o] = acc[o];
    }
}

extern "C" void kernel_launch(void* const* d_in, const int* in_sizes, int n_in,
                              void* d_out, int out_size)
{
    const float* x     = (const float*)d_in[0];
    const float* W_ih0 = (const float*)d_in[1];
    const float* W_hh0 = (const float*)d_in[2];
    const float* b_ih0 = (const float*)d_in[3];
    const float* b_hh0 = (const float*)d_in[4];
    const float* W_ih1 = (const float*)d_in[5];
    const float* W_hh1 = (const float*)d_in[6];
    const float* b_ih1 = (const float*)d_in[7];
    const float* b_hh1 = (const float*)d_in[8];
    const float* W_fc  = (const float*)d_in[9];
    const float* b_fc  = (const float*)d_in[10];
    float* out = (float*)d_out;

    const size_t smem_floats = (size_t)D_IN * G + 3 * (size_t)H * G + 2 * G
                             + OUT_D * H + 8 + 2 * (size_t)H * RP + D_IN * XP;
    const size_t smem_bytes = smem_floats * sizeof(float);   // 226,208 B

    cudaFuncSetAttribute(lstm_fused_kernel,
                         cudaFuncAttributeMaxDynamicSharedMemorySize,
                         (int)smem_bytes);

    lstm_fused_kernel<<<B_TOT / BTILE, NTHREADS, smem_bytes>>>(
        x, W_ih0, W_hh0, b_ih0, b_hh0,
        W_ih1, W_hh1, b_ih1, b_hh1, W_fc, b_fc, out);
}